// round 17
// baseline (speedup 1.0000x reference)
#include <cuda_runtime.h>
#include <cuda_fp16.h>
#include <math.h>

#define BB 8
#define NN 512
#define DMODEL 1024
#define HH 16
#define DK 64

// ---- static scratch ----
__device__ __half g_qh[BB*HH*NN*DK];      // fp16, pre-scaled by 1/8
__device__ __half g_kh[BB*HH*NN*DK];
__device__ __half g_vh[BB*HH*NN*DK];
__device__ float g_s[BB*HH*NN*NN];        // geometry bias (log g), fp32
__device__ __half g_o1h[BB*NN*DMODEL];    // attn output, fp16 (feeds O-proj)
__device__ float g_boxf[BB*NN*6];
__device__ __half g_acth[3*BB*NN*DMODEL]; // fp16 activations
__device__ __half g_wh[4*DMODEL*DMODEL];  // fp16 weights Wq,Wk,Wv,Wo

// ---- side stream + events (host objects only, static init) ----
static cudaStream_t g_s2;
static cudaEvent_t g_evFork, g_evJoin;
static struct StreamInit {
    StreamInit() {
        cudaStreamCreateWithFlags(&g_s2, cudaStreamNonBlocking);
        cudaEventCreateWithFlags(&g_evFork, cudaEventDisableTiming);
        cudaEventCreateWithFlags(&g_evJoin, cudaEventDisableTiming);
    }
} g_streamInit;

// ---- helpers ----
__device__ __forceinline__ void mma16h(float* c, const unsigned* a,
                                       unsigned b0, unsigned b1) {
    asm volatile("mma.sync.aligned.m16n8k16.row.col.f32.f16.f16.f32 "
        "{%0,%1,%2,%3},{%4,%5,%6,%7},{%8,%9},{%0,%1,%2,%3};"
        : "+f"(c[0]), "+f"(c[1]), "+f"(c[2]), "+f"(c[3])
        : "r"(a[0]), "r"(a[1]), "r"(a[2]), "r"(a[3]), "r"(b0), "r"(b1));
}
__device__ __forceinline__ void ldsm4(unsigned& r0, unsigned& r1, unsigned& r2v,
                                      unsigned& r3, unsigned a) {
    asm volatile("ldmatrix.sync.aligned.m8n8.x4.shared.b16 {%0,%1,%2,%3}, [%4];"
        : "=r"(r0), "=r"(r1), "=r"(r2v), "=r"(r3) : "r"(a));
}
__device__ __forceinline__ void ldsm4t(unsigned& r0, unsigned& r1, unsigned& r2v,
                                       unsigned& r3, unsigned a) {
    asm volatile("ldmatrix.sync.aligned.m8n8.x4.trans.shared.b16 {%0,%1,%2,%3}, [%4];"
        : "=r"(r0), "=r"(r1), "=r"(r2v), "=r"(r3) : "r"(a));
}
__device__ __forceinline__ void cpa16(unsigned dst, const void* src) {
    asm volatile("cp.async.cg.shared.global [%0], [%1], 16;" :: "r"(dst), "l"(src));
}
__device__ __forceinline__ void cp_commit() {
    asm volatile("cp.async.commit_group;" ::: "memory");
}
__device__ __forceinline__ void cp_wait1() {
    asm volatile("cp.async.wait_group 1;" ::: "memory");
}
__device__ __forceinline__ void cp_wait0() {
    asm volatile("cp.async.wait_group 0;" ::: "memory");
}
__device__ __forceinline__ unsigned smaddr(const void* p) {
    return (unsigned)__cvta_generic_to_shared(p);
}

// ============================================================
// box features
// ============================================================
__global__ void boxfeat_kernel(const float* __restrict__ boxes) {
    int i = blockIdx.x * blockDim.x + threadIdx.x;
    if (i >= BB*NN) return;
    float4 bx = ((const float4*)boxes)[i];
    float cx = 0.5f * (bx.x + bx.z);
    float cy = 0.5f * (bx.y + bx.w);
    float w  = bx.z - bx.x + 1.0f;
    float h  = bx.w - bx.y + 1.0f;
    float* o = &g_boxf[i*6];
    o[0] = cx; o[1] = cy;
    o[2] = 1.0f / w; o[3] = 1.0f / h;
    o[4] = __logf(w); o[5] = __logf(h);
}

// ============================================================
// convert activations + weights to fp16
// ============================================================
__global__ void prep_kernel(const float* __restrict__ q, const float* __restrict__ k,
                            const float* __restrict__ v, const float* __restrict__ wq,
                            const float* __restrict__ wk, const float* __restrict__ wv,
                            const float* __restrict__ wo) {
    int z = blockIdx.y;
    const float* src = (z==0)?q:(z==1)?k:(z==2)?v:(z==3)?wq:(z==4)?wk:(z==5)?wv:wo;
    __half* dst = (z < 3) ? g_acth + (size_t)z*(BB*NN*DMODEL)
                          : g_wh + (size_t)(z-3)*(DMODEL*DMODEL);
    int n4 = (z < 3) ? (BB*NN*DMODEL/4) : (DMODEL*DMODEL/4);
    int i = blockIdx.x*256 + threadIdx.x;
    if (i < n4) {
        float4 a = ((const float4*)src)[i];
        ((__half2*)dst)[2*i]   = __floats2half2_rn(a.x, a.y);
        ((__half2*)dst)[2*i+1] = __floats2half2_rn(a.z, a.w);
    }
}

// ============================================================
// geometry bias via tensor cores
// ============================================================
#define EST 72

__global__ void __launch_bounds__(256, 2) geom_kernel(const float* __restrict__ Wg,
                                                      const float* __restrict__ bg) {
    __shared__ __half Es[256][EST];
    __shared__ __half Wgh[16][EST];
    __shared__ float qf[16][6];
    __shared__ float kf[16][6];
    __shared__ float bgs[16];
    int tid = threadIdx.x;
    int b  = blockIdx.z;
    int q0 = blockIdx.y * 16, k0 = blockIdx.x * 16;

    {
        int i = tid * 4;
        float4 wv = *(const float4*)(Wg + i);
        int h = i >> 6, d = i & 63;
        Wgh[h][d+0] = __float2half(wv.x);
        Wgh[h][d+1] = __float2half(wv.y);
        Wgh[h][d+2] = __float2half(wv.z);
        Wgh[h][d+3] = __float2half(wv.w);
    }
    if (tid < 16) {
        bgs[tid] = bg[tid];
        #pragma unroll
        for (int j = 0; j < 6; j++) qf[tid][j] = g_boxf[(b*NN + q0 + tid)*6 + j];
    } else if (tid < 32) {
        int t = tid - 16;
        #pragma unroll
        for (int j = 0; j < 6; j++) kf[t][j] = g_boxf[(b*NN + k0 + t)*6 + j];
    }
    __syncthreads();

    int ty = tid >> 4, tx = tid & 15;
    float pos[4];
    pos[0] = __logf(fmaxf(fabsf(qf[ty][0] - kf[tx][0]) * qf[ty][2], 1e-3f));
    pos[1] = __logf(fmaxf(fabsf(qf[ty][1] - kf[tx][1]) * qf[ty][3], 1e-3f));
    pos[2] = qf[ty][4] - kf[tx][4];
    pos[3] = qf[ty][5] - kf[tx][5];

    const float dm[8] = {1.0f, 0.42169650f, 0.17782794f, 0.07498942f,
                         0.03162278f, 0.01333521f, 0.00562341f, 0.00237137f};
    float sv[32], cvv[32];
    #pragma unroll
    for (int c = 0; c < 4; c++) {
        float p100 = 100.0f * pos[c];
        #pragma unroll
        for (int f = 0; f < 8; f++)
            __sincosf(p100 * dm[f], &sv[c*8+f], &cvv[c*8+f]);
    }
    __half2* er = (__half2*)&Es[tid][0];
    #pragma unroll
    for (int d2 = 0; d2 < 16; d2++)
        er[d2] = __floats2half2_rn(sv[2*d2], sv[2*d2+1]);
    #pragma unroll
    for (int d2 = 0; d2 < 16; d2++)
        er[16+d2] = __floats2half2_rn(cvv[2*d2], cvv[2*d2+1]);
    __syncthreads();

    int w = tid >> 5, l = tid & 31;
    int lj   = l & 7;
    int goff = ((l >> 3) & 1) * 8 + lj;
    int khq  = (l >> 4) * 8;

    float acc[2][2][4];
    #pragma unroll
    for (int i = 0; i < 2; i++)
        #pragma unroll
        for (int j = 0; j < 2; j++)
            #pragma unroll
            for (int k = 0; k < 4; k++) acc[i][j][k] = 0.0f;

    #pragma unroll
    for (int kc = 0; kc < 4; kc++) {
        unsigned a[2][4];
        #pragma unroll
        for (int mf = 0; mf < 2; mf++)
            ldsm4(a[mf][0], a[mf][1], a[mf][2], a[mf][3],
                  smaddr(&Es[w*32 + mf*16 + goff][kc*16 + khq]));
        unsigned bb[4];
        ldsm4(bb[0], bb[1], bb[2], bb[3],
              smaddr(&Wgh[goff][kc*16 + khq]));
        #pragma unroll
        for (int mf = 0; mf < 2; mf++) {
            mma16h(acc[mf][0], a[mf], bb[0], bb[2]);
            mma16h(acc[mf][1], a[mf], bb[1], bb[3]);
        }
    }

    #pragma unroll
    for (int mf = 0; mf < 2; mf++) {
        #pragma unroll
        for (int n8 = 0; n8 < 2; n8++) {
            #pragma unroll
            for (int rr = 0; rr < 2; rr++) {
                int p = w*32 + mf*16 + rr*8 + (l >> 2);
                int q = q0 + (p >> 4), k = k0 + (p & 15);
                #pragma unroll
                for (int jj = 0; jj < 2; jj++) {
                    int h = n8*8 + 2*(l & 3) + jj;
                    float v = acc[mf][n8][rr*2 + jj] + bgs[h];
                    g_s[(((size_t)b*HH + h)*NN + q)*NN + k] =
                        __logf(fmaxf(v, 1e-6f));
                }
            }
        }
    }
}

// ============================================================
// fp16 GEMM, 128x256 CTA tile, 8 warps of 64x64 (2m x 4n),
// KTILE=64 halves, 3-stage cp.async, 1 CTA/SM.
// MODE 0: QKV (A=g_acth[z], B=g_wh[z], fp16 scatter, z==0 scaled 1/8)
// MODE 1: O-proj (A=g_o1h, B=g_wh[3], dst=Cout, fp32)
// ============================================================
#define HST 72                               // smem row stride in halves
#define ATILE (128*HST)
#define BTILE (256*HST)
#define STAGEH (ATILE + BTILE)               // 27648 halves per stage
#define HSMEM (3 * STAGEH * 2)               // 165888 B

template<int MODE>
__global__ void __launch_bounds__(256, 1) gemm_tc(
    const float* __restrict__ b0p, const float* __restrict__ b1p,
    const float* __restrict__ b2p, float* __restrict__ Cout)
{
    constexpr int KD  = DMODEL;
    constexpr int NIT = KD / 64;
    extern __shared__ __half hsm[];

    int t = threadIdx.x;
    int m0 = blockIdx.y * 128, n0 = blockIdx.x * 256;
    int z = blockIdx.z;

    const __half *A, *B;
    const float *bias;
    if (MODE == 0) {
        A = g_acth + (size_t)z*(BB*NN*DMODEL);
        B = g_wh   + (size_t)z*(DMODEL*DMODEL);
        bias = (z == 0) ? b0p : (z == 1) ? b1p : b2p;
    } else {
        A = g_o1h;
        B = g_wh + 3*(size_t)(DMODEL*DMODEL);
        bias = b0p;
    }

    // loader slots: A 4 chunks/thr (128 rows x 8), B 8 chunks/thr (256 x 8)
    int arow[4], acol[4], brow[8], bcol[8];
    #pragma unroll
    for (int i = 0; i < 4; i++) {
        int idx = t + i*256;
        arow[i] = idx >> 3; acol[i] = (idx & 7) * 8;
    }
    #pragma unroll
    for (int i = 0; i < 8; i++) {
        int idx = t + i*256;
        brow[i] = idx >> 3; bcol[i] = (idx & 7) * 8;
    }
    unsigned sbase = smaddr(hsm);

    int w = t >> 5, l = t & 31;
    int wm = w & 1, wn = w >> 1;             // 2(m) x 4(n) warps of 64x64
    int lj   = l & 7;
    int goff = ((l >> 3) & 1) * 8 + lj;
    int khq  = (l >> 4) * 8;

    float acc[4][8][4];
    #pragma unroll
    for (int i = 0; i < 4; i++)
        #pragma unroll
        for (int j = 0; j < 8; j++)
            #pragma unroll
            for (int k = 0; k < 4; k++) acc[i][j][k] = 0.0f;

    #pragma unroll
    for (int p = 0; p < 2; p++) {
        unsigned ab = sbase + (unsigned)(p*STAGEH)*2u;
        #pragma unroll
        for (int i = 0; i < 4; i++)
            cpa16(ab + (arow[i]*HST + acol[i])*2u,
                  A + (size_t)(m0 + arow[i])*KD + p*64 + acol[i]);
        #pragma unroll
        for (int i = 0; i < 8; i++)
            cpa16(ab + (ATILE + brow[i]*HST + bcol[i])*2u,
                  B + (size_t)(n0 + brow[i])*KD + p*64 + bcol[i]);
        cp_commit();
    }

    for (int j = 0; j < NIT; j++) {
        cp_wait1();
        __syncthreads();
        if (j + 2 < NIT) {
            int s = (j + 2) % 3;
            unsigned ab = sbase + (unsigned)(s*STAGEH)*2u;
            int kb = (j + 2) * 64;
            #pragma unroll
            for (int i = 0; i < 4; i++)
                cpa16(ab + (arow[i]*HST + acol[i])*2u,
                      A + (size_t)(m0 + arow[i])*KD + kb + acol[i]);
            #pragma unroll
            for (int i = 0; i < 8; i++)
                cpa16(ab + (ATILE + brow[i]*HST + bcol[i])*2u,
                      B + (size_t)(n0 + brow[i])*KD + kb + bcol[i]);
        }
        cp_commit();

        int s = j % 3;
        const __half* As = hsm + s*STAGEH;
        const __half* Bs = As + ATILE;
        #pragma unroll
        for (int kc = 0; kc < 4; kc++) {
            unsigned a[4][4];
            #pragma unroll
            for (int mf = 0; mf < 4; mf++)
                ldsm4(a[mf][0], a[mf][1], a[mf][2], a[mf][3],
                      smaddr(&As[(wm*64 + mf*16 + goff)*HST + kc*16 + khq]));
            #pragma unroll
            for (int nt = 0; nt < 4; nt++) {
                unsigned bb[4];
                ldsm4(bb[0], bb[1], bb[2], bb[3],
                      smaddr(&Bs[(wn*64 + nt*16 + goff)*HST + kc*16 + khq]));
                #pragma unroll
                for (int mf = 0; mf < 4; mf++) {
                    mma16h(acc[mf][2*nt],   a[mf], bb[0], bb[2]);
                    mma16h(acc[mf][2*nt+1], a[mf], bb[1], bb[3]);
                }
            }
        }
    }

    float qsc = (MODE == 0 && z == 0) ? 0.125f : 1.0f;
    #pragma unroll
    for (int mf = 0; mf < 4; mf++) {
        #pragma unroll
        for (int nf = 0; nf < 8; nf++) {
            int col = n0 + wn*64 + nf*8 + 2*(l & 3);
            float2 b2 = *(const float2*)(bias + col);
            #pragma unroll
            for (int rr = 0; rr < 2; rr++) {
                int row = m0 + wm*64 + mf*16 + rr*8 + (l >> 2);
                float v0 = acc[mf][nf][rr*2 + 0] + b2.x;
                float v1 = acc[mf][nf][rr*2 + 1] + b2.y;
                if (MODE == 0) {
                    int h = col >> 6, d = col & 63;
                    int bq = row >> 9, ntok = row & (NN-1);
                    __half* dstp = (z == 0) ? g_qh : (z == 1) ? g_kh : g_vh;
                    *(__half2*)&dstp[(((size_t)bq*HH + h)*NN + ntok)*DK + d] =
                        __floats2half2_rn(v0*qsc, v1*qsc);
                } else {
                    *(float2*)&Cout[(size_t)row*DMODEL + col] = make_float2(v0, v1);
                }
            }
        }
    }
}

// ============================================================
// fused attention, fp16 MMAs (unchanged)
// ============================================================
#define QST 72
#define KST 72
#define VST 72
#define FUSED_SMEM ((2*64*KST + 2*64*VST + 128*QST) * 2)

__global__ void __launch_bounds__(256, 2) fused_attn() {
    extern __shared__ __half smh[];
    __half* KsB = smh;
    __half* VsB = smh + 2*64*KST;
    __half* Ps  = VsB + 2*64*VST;

    int t = threadIdx.x;
    int bh = blockIdx.y;
    int q0 = blockIdx.x * 128;
    const __half* Qg = g_qh + ((size_t)bh*NN + q0)*DK;
    const __half* Kg = g_kh + (size_t)bh*NN*DK;
    const __half* Vg = g_vh + (size_t)bh*NN*DK;
    const float*  Sg = g_s  + (size_t)bh*NN*NN;

    int w = t >> 5, l = t & 31;
    int r0 = l >> 2, c0 = l & 3;
    int qrow = w*16 + r0;
    int lj   = l & 7;
    int goff = ((l >> 3) & 1) * 8 + lj;
    int khq  = (l >> 4) * 8;

    #pragma unroll
    for (int i = 0; i < 4; i++) {
        int idx = t + i*256;
        int row = idx >> 3, col = (idx & 7) * 8;
        cpa16(smaddr(Ps + row*QST + col), Qg + row*DK + col);
    }
    #pragma unroll
    for (int i = 0; i < 2; i++) {
        int idx = t + i*256;
        int row = idx >> 3, col = (idx & 7) * 8;
        cpa16(smaddr(KsB + row*KST + col), Kg + row*DK + col);
        cpa16(smaddr(VsB + row*VST + col), Vg + row*DK + col);
    }
    cp_commit();
    cp_wait0();
    __syncthreads();

    unsigned qa[4][4];
    #pragma unroll
    for (int kc = 0; kc < 4; kc++)
        ldsm4(qa[kc][0], qa[kc][1], qa[kc][2], qa[kc][3],
              smaddr(&Ps[(w*16 + goff)*QST + kc*16 + khq]));
    __syncthreads();

    float Oa[8][4];
    #pragma unroll
    for (int nf = 0; nf < 8; nf++)
        #pragma unroll
        for (int k = 0; k < 4; k++) Oa[nf][k] = 0.0f;
    float m0v = -INFINITY, m1v = -INFINITY, l0v = 0.0f, l1v = 0.0f;

    const int NT = NN / 64;
    for (int j = 0; j < NT; j++) {
        if (j > 0) {
            cp_wait0();
            __syncthreads();
        }
        if (j + 1 < NT) {
            int nb = (j + 1) & 1;
            __half* Ksn = KsB + nb*64*KST;
            __half* Vsn = VsB + nb*64*VST;
            #pragma unroll
            for (int i = 0; i < 2; i++) {
                int idx = t + i*256;
                int row = idx >> 3, col = (idx & 7) * 8;
                cpa16(smaddr(Ksn + row*KST + col), Kg + ((j+1)*64 + row)*DK + col);
                cpa16(smaddr(Vsn + row*VST + col), Vg + ((j+1)*64 + row)*DK + col);
            }
        }
        cp_commit();

        const __half* Ks = KsB + (j & 1)*64*KST;
        const __half* Vs = VsB + (j & 1)*64*VST;

        float acc[8][4];
        {
            const float* br0 = Sg + (size_t)(q0 + qrow)*NN + j*64;
            const float* br1 = br0 + 8*NN;
            #pragma unroll
            for (int nf = 0; nf < 8; nf++) {
                float2 t0 = *(const float2*)(br0 + nf*8 + 2*c0);
                float2 t1 = *(const float2*)(br1 + nf*8 + 2*c0);
                acc[nf][0] = t0.x; acc[nf][1] = t0.y;
                acc[nf][2] = t1.x; acc[nf][3] = t1.y;
            }
        }
        #pragma unroll
        for (int kc = 0; kc < 4; kc++) {
            #pragma unroll
            for (int nt = 0; nt < 4; nt++) {
                unsigned bb[4];
                ldsm4(bb[0], bb[1], bb[2], bb[3],
                      smaddr(&Ks[(nt*16 + goff)*KST + kc*16 + khq]));
                mma16h(acc[2*nt],   qa[kc], bb[0], bb[2]);
                mma16h(acc[2*nt+1], qa[kc], bb[1], bb[3]);
            }
        }

        float mx0 = -INFINITY, mx1 = -INFINITY;
        #pragma unroll
        for (int nf = 0; nf < 8; nf++) {
            mx0 = fmaxf(mx0, fmaxf(acc[nf][0], acc[nf][1]));
            mx1 = fmaxf(mx1, fmaxf(acc[nf][2], acc[nf][3]));
        }
        #pragma unroll
        for (int o = 1; o <= 2; o <<= 1) {
            mx0 = fmaxf(mx0, __shfl_xor_sync(0xffffffffu, mx0, o));
            mx1 = fmaxf(mx1, __shfl_xor_sync(0xffffffffu, mx1, o));
        }
        float mn0 = fmaxf(m0v, mx0), mn1 = fmaxf(m1v, mx1);
        float sc0 = __expf(m0v - mn0), sc1 = __expf(m1v - mn1);
        m0v = mn0; m1v = mn1;
        float s0 = 0.0f, s1 = 0.0f;
        #pragma unroll
        for (int nf = 0; nf < 8; nf++) {
            acc[nf][0] = __expf(acc[nf][0] - mn0);
            acc[nf][1] = __expf(acc[nf][1] - mn0);
            acc[nf][2] = __expf(acc[nf][2] - mn1);
            acc[nf][3] = __expf(acc[nf][3] - mn1);
            s0 += acc[nf][0] + acc[nf][1];
            s1 += acc[nf][2] + acc[nf][3];
        }
        #pragma unroll
        for (int o = 1; o <= 2; o <<= 1) {
            s0 += __shfl_xor_sync(0xffffffffu, s0, o);
            s1 += __shfl_xor_sync(0xffffffffu, s1, o);
        }
        l0v = l0v * sc0 + s0;
        l1v = l1v * sc1 + s1;
        #pragma unroll
        for (int nf = 0; nf < 8; nf++) {
            Oa[nf][0] *= sc0; Oa[nf][1] *= sc0;
            Oa[nf][2] *= sc1; Oa[nf][3] *= sc1;
        }

        #pragma unroll
        for (int nf = 0; nf < 8; nf++) {
            *(__half2*)&Ps[qrow*QST     + nf*8 + 2*c0] =
                __floats2half2_rn(acc[nf][0], acc[nf][1]);
            *(__half2*)&Ps[(qrow+8)*QST + nf*8 + 2*c0] =
                __floats2half2_rn(acc[nf][2], acc[nf][3]);
        }
        __syncwarp();
        #pragma unroll
        for (int kc = 0; kc < 4; kc++) {
            unsigned a4[4];
            ldsm4(a4[0], a4[1], a4[2], a4[3],
                  smaddr(&Ps[(w*16 + goff)*QST + kc*16 + khq]));
            #pragma unroll
            for (int dt = 0; dt < 4; dt++) {
                unsigned vb[4];
                ldsm4t(vb[0], vb[1], vb[2], vb[3],
                       smaddr(&Vs[(kc*16 + goff)*VST + dt*16 + khq]));
                mma16h(Oa[2*dt],   a4, vb[0], vb[1]);
                mma16h(Oa[2*dt+1], a4, vb[2], vb[3]);
            }
        }
        __syncwarp();
    }

    float inv0 = 1.0f / l0v, inv1 = 1.0f / l1v;
    int b = bh >> 4, h = bh & 15;
    __half* O0 = g_o1h + ((size_t)b*NN + q0 + qrow)*DMODEL + h*DK;
    __half* O1 = O0 + 8*DMODEL;
    #pragma unroll
    for (int nf = 0; nf < 8; nf++) {
        *(__half2*)(O0 + nf*8 + 2*c0) = __floats2half2_rn(Oa[nf][0]*inv0, Oa[nf][1]*inv0);
        *(__half2*)(O1 + nf*8 + 2*c0) = __floats2half2_rn(Oa[nf][2]*inv1, Oa[nf][3]*inv1);
    }
}

// ============================================================
extern "C" void kernel_launch(void* const* d_in, const int* in_sizes, int n_in,
                              void* d_out, int out_size) {
    const float* queries = (const float*)d_in[0];
    const float* keys    = (const float*)d_in[1];
    const float* values  = (const float*)d_in[2];
    const float* boxes   = (const float*)d_in[3];
    const float* Wq = (const float*)d_in[4];
    const float* bq = (const float*)d_in[5];
    const float* Wk = (const float*)d_in[6];
    const float* bk = (const float*)d_in[7];
    const float* Wv = (const float*)d_in[8];
    const float* bv = (const float*)d_in[9];
    const float* Wo = (const float*)d_in[10];
    const float* bo = (const float*)d_in[11];
    const float* Wg = (const float*)d_in[12];
    const float* bg = (const float*)d_in[13];
    float* out = (float*)d_out;

    cudaFuncSetAttribute(gemm_tc<0>, cudaFuncAttributeMaxDynamicSharedMemorySize, HSMEM);
    cudaFuncSetAttribute(gemm_tc<1>, cudaFuncAttributeMaxDynamicSharedMemorySize, HSMEM);
    cudaFuncSetAttribute(fused_attn, cudaFuncAttributeMaxDynamicSharedMemorySize,
                         FUSED_SMEM);

    // fork: side stream runs geometry-bias chain; join before fused_attn
    cudaEventRecord(g_evFork, 0);
    cudaStreamWaitEvent(g_s2, g_evFork, 0);

    boxfeat_kernel<<<16, 256, 0, g_s2>>>(boxes);
    geom_kernel<<<dim3(32, 32, 8), 256, 0, g_s2>>>(Wg, bg);
    cudaEventRecord(g_evJoin, g_s2);

    prep_kernel<<<dim3(4096, 7), 256>>>(queries, keys, values, Wq, Wk, Wv, Wo);
    gemm_tc<0><<<dim3(4, 32, 3), 256, HSMEM>>>(bq, bk, bv, nullptr);

    cudaStreamWaitEvent(0, g_evJoin, 0);
    fused_attn<<<dim3(4, 128), 256, FUSED_SMEM>>>();
    gemm_tc<1><<<dim3(4, 32, 1), 256, HSMEM>>>(bo, nullptr, nullptr, out);
}